// round 5
// baseline (speedup 1.0000x reference)
#include <cuda_runtime.h>
#include <cfloat>

#define BB    4
#define NN    16384
#define MM    1024
#define CC    64
#define COP   64
#define COUT  128
#define KK    32
#define R2    0.25f
#define NI    67        // 3 rel + 64 feat
#define FS    69        // s_F row stride in floats: 8*69 mod 32 = 8 -> conflict-free kt rows
#define G     4         // centers per CTA, one per warp

// Packed dual-FMA on Blackwell: d = a*b + c per 32-bit lane.
__device__ __forceinline__ float2 ffma2(float2 a, float2 b, float2 c) {
    float2 d;
    asm("{\n"
        ".reg .b64 ra, rb, rc, rd;\n"
        "mov.b64 ra, {%2, %3};\n"
        "mov.b64 rb, {%4, %5};\n"
        "mov.b64 rc, {%6, %7};\n"
        "fma.rn.f32x2 rd, ra, rb, rc;\n"
        "mov.b64 {%0, %1}, rd;\n"
        "}"
        : "=f"(d.x), "=f"(d.y)
        : "f"(a.x), "f"(a.y), "f"(b.x), "f"(b.y), "f"(c.x), "f"(c.y));
    return d;
}

__global__ __launch_bounds__(128)
void pointnet_sampler_kernel(
    const float* __restrict__ positions,   // (B, N, 3)
    const float* __restrict__ features,    // (B, N, 64)
    const float* __restrict__ centers,     // (B, M, 3)
    const float* __restrict__ distances,   // (B, M, N)
    const float* __restrict__ W_op,        // (67, 64)
    const float* __restrict__ b_op,        // (64)
    const float* __restrict__ W_agg,       // (64, 128)
    const float* __restrict__ b_agg,       // (128)
    float* __restrict__ out)               // (B, M, 128)
{
    const int blk  = blockIdx.x;            // 0..1023
    const int b    = blk >> 8;
    const int tid  = threadIdx.x;
    const int lane = tid & 31;
    const int g    = tid >> 5;              // warp == center slot
    const int m    = (blk & 255) * G + g;   // this warp's center
    const int kt   = lane >> 3;             // k-tile: k in [8kt, 8kt+8)
    const int ct   = lane & 7;              // c-tile: c in [8ct, 8ct+8)

    // [g][k*FS + i]: i=0..2 rel, i=3+c feat  (warp-private slabs)
    __shared__ float s_F[G][KK * FS];
    __shared__ int   s_idx[G][KK];
    __shared__ __align__(16) float s_pool[G][COP];

    // ---- Phase A: ball query (each warp its own center) ----
    const float* drow = distances + ((size_t)b * MM + m) * NN;
    float dv[8];
#pragma unroll
    for (int j = 0; j < 8; j++) dv[j] = drow[j * 32 + lane];

    int count = 0;
#pragma unroll
    for (int j = 0; j < 8; j++) {
        if (count < KK) {                    // warp-uniform
            bool v = dv[j] < R2;
            unsigned msk = __ballot_sync(0xffffffffu, v);
            int pre = __popc(msk & ((1u << lane) - 1u));
            if (v && count + pre < KK) s_idx[g][count + pre] = j * 32 + lane;
            count += __popc(msk);
        }
    }
    int base = 256;
    while (count < KK && base < NN) {        // rare fallback
        float d = drow[base + lane];
        bool v = d < R2;
        unsigned msk = __ballot_sync(0xffffffffu, v);
        int pre = __popc(msk & ((1u << lane) - 1u));
        if (v && count + pre < KK) s_idx[g][count + pre] = base + lane;
        count += __popc(msk);
        base += 32;
    }
    const int V = min(count, KK);            // warp-uniform register
    __syncwarp();

    // ---- rel-pos rows: lane = k ----
    {
        const float* cp = centers + ((size_t)b * MM + m) * 3;
        float cx = cp[0], cy = cp[1], cz = cp[2];
        if (lane < V) {
            const float* pp = positions + ((size_t)b * NN + s_idx[g][lane]) * 3;
            float* r = &s_F[g][lane * FS];
            r[0] = pp[0] - cx;
            r[1] = pp[1] - cy;
            r[2] = pp[2] - cz;
        }
    }

    // ---- feature gather: 32 rows x 16 chunks, 2 rows per warp-inst ----
    {
        const float* featb = features + (size_t)b * NN * CC;
        const int c4 = lane & 15;            // 16B chunk within row
        const int kb2 = lane >> 4;           // 0/1
#pragma unroll
        for (int jj = 0; jj < 4; jj++) {     // batches of 4 for MLP
            float4 v[4];
            int krow[4];
#pragma unroll
            for (int j = 0; j < 4; j++) {
                int k = kb2 + 2 * (4 * jj + j);
                krow[j] = k;
                int id = (k < V) ? s_idx[g][k] : 0;
                v[j] = *reinterpret_cast<const float4*>(featb + (size_t)id * CC + c4 * 4);
            }
#pragma unroll
            for (int j = 0; j < 4; j++) {
                float* r = &s_F[g][krow[j] * FS + 3 + c4 * 4];
                r[0] = v[j].x; r[1] = v[j].y; r[2] = v[j].z; r[3] = v[j].w;
            }
        }
    }
    __syncwarp();

    // ---- Phase B: 8k x 8c register tile GEMM over i = 0..66 ----
    float2 acc[4][8];                        // [k-pair][c]
#pragma unroll
    for (int p = 0; p < 4; p++)
#pragma unroll
        for (int c = 0; c < 8; c++) acc[p][c] = make_float2(0.f, 0.f);

    const float* xrow = &s_F[g][8 * kt * FS];   // + j*FS + i
    const float* wrow = W_op + 8 * ct;
#pragma unroll 4
    for (int i = 0; i < NI; i++) {
        float x0 = xrow[0 * FS + i], x1 = xrow[1 * FS + i];
        float x2 = xrow[2 * FS + i], x3 = xrow[3 * FS + i];
        float x4 = xrow[4 * FS + i], x5 = xrow[5 * FS + i];
        float x6 = xrow[6 * FS + i], x7 = xrow[7 * FS + i];
        float4 wA = __ldg(reinterpret_cast<const float4*>(wrow + i * COP));
        float4 wB = __ldg(reinterpret_cast<const float4*>(wrow + i * COP + 4));
        float2 xp[4] = { {x0,x1}, {x2,x3}, {x4,x5}, {x6,x7} };
        const float wv[8] = { wA.x, wA.y, wA.z, wA.w, wB.x, wB.y, wB.z, wB.w };
#pragma unroll
        for (int p = 0; p < 4; p++)
#pragma unroll
            for (int c = 0; c < 8; c++)
                acc[p][c] = ffma2(xp[p], make_float2(wv[c], wv[c]), acc[p][c]);
    }

    // ---- bias + masked max over this thread's 8 k's ----
    float4 boA = __ldg(reinterpret_cast<const float4*>(b_op + 8 * ct));
    float4 boB = __ldg(reinterpret_cast<const float4*>(b_op + 8 * ct + 4));
    const float bo[8] = { boA.x, boA.y, boA.z, boA.w, boB.x, boB.y, boB.z, boB.w };
    const int kb = 8 * kt;
    float mx[8];
#pragma unroll
    for (int c = 0; c < 8; c++) mx[c] = -FLT_MAX;
#pragma unroll
    for (int p = 0; p < 4; p++) {
        bool v0 = (kb + 2 * p)     < V;
        bool v1 = (kb + 2 * p + 1) < V;
#pragma unroll
        for (int c = 0; c < 8; c++) {
            if (v0) mx[c] = fmaxf(mx[c], acc[p][c].x + bo[c]);
            if (v1) mx[c] = fmaxf(mx[c], acc[p][c].y + bo[c]);
        }
    }
    // reduce over kt (lanes +-8, +-16 share ct)
#pragma unroll
    for (int d = 8; d < 32; d <<= 1)
#pragma unroll
        for (int c = 0; c < 8; c++)
            mx[c] = fmaxf(mx[c], __shfl_xor_sync(0xffffffffu, mx[c], d));

    if (kt == 0) {
        float z = (V < KK) ? 0.f : -FLT_MAX;  // zero row joins max iff a slot invalid
        float* pp = &s_pool[g][8 * ct];
        *reinterpret_cast<float4*>(pp) =
            make_float4(fmaxf(mx[0], z), fmaxf(mx[1], z), fmaxf(mx[2], z), fmaxf(mx[3], z));
        *reinterpret_cast<float4*>(pp + 4) =
            make_float4(fmaxf(mx[4], z), fmaxf(mx[5], z), fmaxf(mx[6], z), fmaxf(mx[7], z));
    }
    __syncwarp();

    // ---- Phase C: aggregator (64 -> 128) + ReLU; 4 outputs per lane ----
    float4 bg = __ldg(reinterpret_cast<const float4*>(b_agg + 4 * lane));
    float2 a01 = make_float2(bg.x, bg.y);
    float2 a23 = make_float2(bg.z, bg.w);
    const float* pool = s_pool[g];
#pragma unroll 8
    for (int cc = 0; cc < COP; cc++) {
        float p = pool[cc];                  // broadcast LDS
        float4 w = __ldg(reinterpret_cast<const float4*>(W_agg + cc * COUT + 4 * lane));
        a01 = ffma2(make_float2(w.x, w.y), make_float2(p, p), a01);
        a23 = ffma2(make_float2(w.z, w.w), make_float2(p, p), a23);
    }
    float4 o = make_float4(fmaxf(a01.x, 0.f), fmaxf(a01.y, 0.f),
                           fmaxf(a23.x, 0.f), fmaxf(a23.y, 0.f));
    *reinterpret_cast<float4*>(out + ((size_t)b * MM + m) * COUT + 4 * lane) = o;
}

extern "C" void kernel_launch(void* const* d_in, const int* in_sizes, int n_in,
                              void* d_out, int out_size)
{
    (void)in_sizes; (void)n_in; (void)out_size;
    pointnet_sampler_kernel<<<BB * MM / G, 128>>>(
        (const float*)d_in[0],  // positions
        (const float*)d_in[1],  // features
        (const float*)d_in[2],  // centers
        (const float*)d_in[3],  // distances
        (const float*)d_in[4],  // W_op
        (const float*)d_in[5],  // b_op
        (const float*)d_in[6],  // W_agg
        (const float*)d_in[7],  // b_agg
        (float*)d_out);
}

// round 6
// speedup vs baseline: 1.8673x; 1.8673x over previous
#include <cuda_runtime.h>
#include <cfloat>

#define BB    4
#define NN    16384
#define MM    1024
#define CC    64
#define COP   64
#define COUT  128
#define KK    32
#define R2    0.25f
#define XS    76        // s_X row stride (floats): kt*76 mod 32 = {0,12,24,4,16,28,8,20} conflict-free
#define G     2         // centers per CTA

// Packed dual-FMA on Blackwell: d = a*b + c per 32-bit lane.
__device__ __forceinline__ float2 ffma2(float2 a, float2 b, float2 c) {
    float2 d;
    asm("{\n"
        ".reg .b64 ra, rb, rc, rd;\n"
        "mov.b64 ra, {%2, %3};\n"
        "mov.b64 rb, {%4, %5};\n"
        "mov.b64 rc, {%6, %7};\n"
        "fma.rn.f32x2 rd, ra, rb, rc;\n"
        "mov.b64 {%0, %1}, rd;\n"
        "}"
        : "=f"(d.x), "=f"(d.y)
        : "f"(a.x), "f"(a.y), "f"(b.x), "f"(b.y), "f"(c.x), "f"(c.y));
    return d;
}

__global__ __launch_bounds__(128)
void pointnet_sampler_kernel(
    const float* __restrict__ positions,   // (B, N, 3)
    const float* __restrict__ features,    // (B, N, 64)
    const float* __restrict__ centers,     // (B, M, 3)
    const float* __restrict__ distances,   // (B, M, N)
    const float* __restrict__ W_op,        // (67, 64)  rows: 0..2 rel, 3..66 feat
    const float* __restrict__ b_op,        // (64)
    const float* __restrict__ W_agg,       // (64, 128)
    const float* __restrict__ b_agg,       // (128)
    float* __restrict__ out)               // (B, M, 128)
{
    const int blk  = blockIdx.x;            // 0..2047
    const int b    = blk >> 9;
    const int m0   = (blk & 511) * G;
    const int tid  = threadIdx.x;
    const int lane = tid & 31;
    const int wid  = tid >> 5;
    const int ktl  = lane & 7;              // k = ktl + 8j, j=0..3
    const int ct4  = lane >> 3;             // 0..3
    const int cb   = 16 * wid + 4 * ct4;    // this thread's 4 c-channels

    // s_X[g][k][0..63]=features, [64..66]=rel, [67..75] pad
    __shared__ float    s_X[G][KK][XS];
    __shared__ int      s_idx[G][KK];
    __shared__ unsigned s_msk[G][8];
    __shared__ int      s_V[G];
    __shared__ __align__(16) float s_pool[G][COP];

    // ---- A0: all 4 warps ballot 4 distance chunks each (2 warps per center) ----
    {
        const int g0 = wid >> 1, half = wid & 1;
        const float* drow = distances + ((size_t)b * MM + m0 + g0) * NN;
        float d[4];
#pragma unroll
        for (int j = 0; j < 4; j++) d[j] = drow[(4 * half + j) * 32 + lane];
#pragma unroll
        for (int j = 0; j < 4; j++) {
            unsigned msk = __ballot_sync(0xffffffffu, d[j] < R2);
            if (lane == 0) s_msk[g0][4 * half + j] = msk;
        }
    }
    __syncthreads();

    // ---- A1: warps 0,1 build index lists from masks ----
    if (wid < G) {
        int count = 0;
#pragma unroll
        for (int ch = 0; ch < 8; ch++) {
            if (count < KK) {                // warp-uniform
                unsigned msk = s_msk[wid][ch];
                bool v = (msk >> lane) & 1u;
                int pre = __popc(msk & ((1u << lane) - 1u));
                if (v && count + pre < KK) s_idx[wid][count + pre] = ch * 32 + lane;
                count += __popc(msk);
            }
        }
        const float* drow = distances + ((size_t)b * MM + m0 + wid) * NN;
        int base = 256;
        while (count < KK && base < NN) {    // rare fallback (~1% of rows)
            float d = drow[base + lane];
            bool v = d < R2;
            unsigned msk = __ballot_sync(0xffffffffu, v);
            int pre = __popc(msk & ((1u << lane) - 1u));
            if (v && count + pre < KK) s_idx[wid][count + pre] = base + lane;
            count += __popc(msk);
            base += 32;
        }
        if (lane == 0) s_V[wid] = min(count, KK);
    }
    __syncthreads();
    const int V0 = s_V[0], V1 = s_V[1];

    // ---- A2: gather features directly into s_X (no staging, no transpose) ----
    const float* featb = features + (size_t)b * NN * CC;
#pragma unroll
    for (int g = 0; g < G; g++) {
        const int V = g ? V1 : V0;
        float4 v[4];
        int kr[4];
#pragma unroll
        for (int j = 0; j < 4; j++) {
            int cid = tid + 128 * j;
            int k = cid >> 4;
            kr[j] = k;
            int id = (k < V) ? s_idx[g][k] : 0;
            v[j] = *reinterpret_cast<const float4*>(featb + (size_t)id * CC + (cid & 15) * 4);
        }
#pragma unroll
        for (int j = 0; j < 4; j++) {
            int cid = tid + 128 * j;
            *reinterpret_cast<float4*>(&s_X[g][kr[j]][(cid & 15) * 4]) = v[j];
        }
    }
    // rel-pos: threads 0..63, one (g,k) each
    if (tid < G * KK) {
        int g = tid >> 5, k = tid & 31;
        int Vg = g ? V1 : V0;
        if (k < Vg) {
            const float* cp = centers   + ((size_t)b * MM + m0 + g) * 3;
            const float* pp = positions + ((size_t)b * NN + s_idx[g][k]) * 3;
            s_X[g][k][64] = pp[0] - cp[0];
            s_X[g][k][65] = pp[1] - cp[1];
            s_X[g][k][66] = pp[2] - cp[2];
        }
    }
    __syncthreads();

    // ---- Phase B: GEMM. acc[g][jp][cc], jp packs k-pair {ktl+16jp, ktl+16jp+8} ----
    float2 acc[G][2][4];
#pragma unroll
    for (int g = 0; g < G; g++)
#pragma unroll
        for (int jp = 0; jp < 2; jp++)
#pragma unroll
            for (int cc = 0; cc < 4; cc++) acc[g][jp][cc] = make_float2(0.f, 0.f);

    // main: feature i-blocks (X idx f0..f0+3  <->  W rows 3+f0 .. 3+f0+3)
#pragma unroll 4
    for (int ib = 0; ib < 16; ib++) {
        const int f0 = 4 * ib;
        float4 xr[G][4];
#pragma unroll
        for (int g = 0; g < G; g++)
#pragma unroll
            for (int j = 0; j < 4; j++)
                xr[g][j] = *reinterpret_cast<const float4*>(&s_X[g][ktl + 8 * j][f0]);
#pragma unroll
        for (int r = 0; r < 4; r++) {
            float4 w = __ldg(reinterpret_cast<const float4*>(
                W_op + (size_t)(3 + f0 + r) * COP + cb));
            const float wv[4] = { w.x, w.y, w.z, w.w };
#pragma unroll
            for (int g = 0; g < G; g++)
#pragma unroll
                for (int jp = 0; jp < 2; jp++) {
                    float2 x = make_float2(
                        reinterpret_cast<const float*>(&xr[g][2 * jp])[r],
                        reinterpret_cast<const float*>(&xr[g][2 * jp + 1])[r]);
#pragma unroll
                    for (int cc = 0; cc < 4; cc++)
                        acc[g][jp][cc] = ffma2(x, make_float2(wv[cc], wv[cc]), acc[g][jp][cc]);
                }
        }
    }
    // tail: rel terms (X idx 64..66 <-> W rows 0..2)
    {
        float4 xr[G][4];
#pragma unroll
        for (int g = 0; g < G; g++)
#pragma unroll
            for (int j = 0; j < 4; j++)
                xr[g][j] = *reinterpret_cast<const float4*>(&s_X[g][ktl + 8 * j][64]);
#pragma unroll
        for (int r = 0; r < 3; r++) {
            float4 w = __ldg(reinterpret_cast<const float4*>(W_op + (size_t)r * COP + cb));
            const float wv[4] = { w.x, w.y, w.z, w.w };
#pragma unroll
            for (int g = 0; g < G; g++)
#pragma unroll
                for (int jp = 0; jp < 2; jp++) {
                    float2 x = make_float2(
                        reinterpret_cast<const float*>(&xr[g][2 * jp])[r],
                        reinterpret_cast<const float*>(&xr[g][2 * jp + 1])[r]);
#pragma unroll
                    for (int cc = 0; cc < 4; cc++)
                        acc[g][jp][cc] = ffma2(x, make_float2(wv[cc], wv[cc]), acc[g][jp][cc]);
                }
        }
    }

    // ---- bias + masked max, reduce over ktl (lanes xor 1,2,4) ----
    float4 bo = __ldg(reinterpret_cast<const float4*>(b_op + cb));
    const float bv[4] = { bo.x, bo.y, bo.z, bo.w };
#pragma unroll
    for (int g = 0; g < G; g++) {
        const int V = g ? V1 : V0;
        float mx[4] = { -FLT_MAX, -FLT_MAX, -FLT_MAX, -FLT_MAX };
#pragma unroll
        for (int jp = 0; jp < 2; jp++) {
            bool vx = (ktl + 16 * jp)     < V;
            bool vy = (ktl + 16 * jp + 8) < V;
#pragma unroll
            for (int cc = 0; cc < 4; cc++) {
                if (vx) mx[cc] = fmaxf(mx[cc], acc[g][jp][cc].x + bv[cc]);
                if (vy) mx[cc] = fmaxf(mx[cc], acc[g][jp][cc].y + bv[cc]);
            }
        }
#pragma unroll
        for (int d = 1; d < 8; d <<= 1)
#pragma unroll
            for (int cc = 0; cc < 4; cc++)
                mx[cc] = fmaxf(mx[cc], __shfl_xor_sync(0xffffffffu, mx[cc], d));
        if (ktl == 0) {
            float z = (V < KK) ? 0.f : -FLT_MAX;
            *reinterpret_cast<float4*>(&s_pool[g][cb]) =
                make_float4(fmaxf(mx[0], z), fmaxf(mx[1], z),
                            fmaxf(mx[2], z), fmaxf(mx[3], z));
        }
    }
    __syncthreads();

    // ---- Phase C: aggregator (64 -> 128) + ReLU; W_agg shared by both centers ----
    float accA = b_agg[tid], accB = accA;
    const float4* p40 = reinterpret_cast<const float4*>(s_pool[0]);
    const float4* p41 = reinterpret_cast<const float4*>(s_pool[1]);
#pragma unroll
    for (int q = 0; q < 16; q++) {
        float4 pA = p40[q];
        float4 pB = p41[q];
        float w0 = __ldg(&W_agg[(4 * q + 0) * COUT + tid]);
        float w1 = __ldg(&W_agg[(4 * q + 1) * COUT + tid]);
        float w2 = __ldg(&W_agg[(4 * q + 2) * COUT + tid]);
        float w3 = __ldg(&W_agg[(4 * q + 3) * COUT + tid]);
        accA = fmaf(pA.x, w0, accA); accB = fmaf(pB.x, w0, accB);
        accA = fmaf(pA.y, w1, accA); accB = fmaf(pB.y, w1, accB);
        accA = fmaf(pA.z, w2, accA); accB = fmaf(pB.z, w2, accB);
        accA = fmaf(pA.w, w3, accA); accB = fmaf(pB.w, w3, accB);
    }
    size_t obase = ((size_t)b * MM + m0) * COUT + tid;
    out[obase]        = fmaxf(accA, 0.f);
    out[obase + COUT] = fmaxf(accB, 0.f);
}

extern "C" void kernel_launch(void* const* d_in, const int* in_sizes, int n_in,
                              void* d_out, int out_size)
{
    (void)in_sizes; (void)n_in; (void)out_size;
    pointnet_sampler_kernel<<<BB * MM / G, 128>>>(
        (const float*)d_in[0],  // positions
        (const float*)d_in[1],  // features
        (const float*)d_in[2],  // centers
        (const float*)d_in[3],  // distances
        (const float*)d_in[4],  // W_op
        (const float*)d_in[5],  // b_op
        (const float*)d_in[6],  // W_agg
        (const float*)d_in[7],  // b_agg
        (float*)d_out);
}

// round 7
// speedup vs baseline: 2.0706x; 1.1088x over previous
#include <cuda_runtime.h>
#include <cfloat>

#define BB    4
#define NN    16384
#define MM    1024
#define CC    64
#define COP   64
#define COUT  128
#define KK    32
#define R2    0.25f
#define NI    67
#define XTS   36        // X^T row stride (floats), 144B
#define G     2         // centers per CTA

typedef unsigned long long ull;

// In-place packed dual-FMA: d.{lo,hi} += x.{lo,hi} * w.{lo,hi}
__device__ __forceinline__ void ffma2p(ull& d, ull x, ull w) {
    asm("fma.rn.f32x2 %0, %1, %2, %0;" : "+l"(d) : "l"(x), "l"(w));
}
__device__ __forceinline__ ull dupf(float w) {
    ull r;
    asm("mov.b64 %0, {%1, %1};" : "=l"(r) : "f"(w));
    return r;
}

__global__ __launch_bounds__(128, 6)
void pointnet_sampler_kernel(
    const float* __restrict__ positions,   // (B, N, 3)
    const float* __restrict__ features,    // (B, N, 64)
    const float* __restrict__ centers,     // (B, M, 3)
    const float* __restrict__ distances,   // (B, M, N)
    const float* __restrict__ W_op,        // (67, 64): rows 0..2 rel, 3..66 feat
    const float* __restrict__ b_op,        // (64)
    const float* __restrict__ W_agg,       // (64, 128)
    const float* __restrict__ b_agg,       // (128)
    float* __restrict__ out)               // (B, M, 128)
{
    const int blk  = blockIdx.x;            // 0..2047
    const int b    = blk >> 9;
    const int m0   = (blk & 511) * G;
    const int tid  = threadIdx.x;
    const int lane = tid & 31;
    const int wid  = tid >> 5;
    const int ktg  = lane & 7;              // k-group: k in [4ktg, 4ktg+4)
    const int ct4  = lane >> 3;             // 0..3
    const int cb   = 16 * wid + 4 * ct4;    // this thread's 4 c-channels

    // X^T[i][colk], colk = (k&3) + 4*((k>>2) ^ S(i)), S(i)= i<3?0:((i-3)>>2)&7
    __shared__ __align__(16) float s_XT[G][NI][XTS];
    __shared__ int      s_idx[G][KK];
    __shared__ unsigned s_msk[G][8];
    __shared__ int      s_V[G];
    __shared__ __align__(16) float s_pool[G][COP];

    // ---- A0: all 4 warps ballot 4 distance chunks each ----
    {
        const int g0 = wid >> 1, half = wid & 1;
        const float* drow = distances + ((size_t)b * MM + m0 + g0) * NN;
        float d[4];
#pragma unroll
        for (int j = 0; j < 4; j++) d[j] = drow[(4 * half + j) * 32 + lane];
#pragma unroll
        for (int j = 0; j < 4; j++) {
            unsigned msk = __ballot_sync(0xffffffffu, d[j] < R2);
            if (lane == 0) s_msk[g0][4 * half + j] = msk;
        }
    }
    __syncthreads();

    // ---- A1: warps 0,1 build index lists ----
    if (wid < G) {
        int count = 0;
#pragma unroll
        for (int ch = 0; ch < 8; ch++) {
            if (count < KK) {
                unsigned msk = s_msk[wid][ch];
                bool v = (msk >> lane) & 1u;
                int pre = __popc(msk & ((1u << lane) - 1u));
                if (v && count + pre < KK) s_idx[wid][count + pre] = ch * 32 + lane;
                count += __popc(msk);
            }
        }
        const float* drow = distances + ((size_t)b * MM + m0 + wid) * NN;
        int base = 256;
        while (count < KK && base < NN) {    // rare fallback
            float d = drow[base + lane];
            bool v = d < R2;
            unsigned msk = __ballot_sync(0xffffffffu, v);
            int pre = __popc(msk & ((1u << lane) - 1u));
            if (v && count + pre < KK) s_idx[wid][count + pre] = base + lane;
            count += __popc(msk);
            base += 32;
        }
        if (lane == 0) s_V[wid] = min(count, KK);
    }
    __syncthreads();
    const int V0 = s_V[0], V1 = s_V[1];

    // ---- A2: coalesced gather -> swizzled transposed store ----
    const float* featb = features + (size_t)b * NN * CC;
#pragma unroll
    for (int g = 0; g < G; g++) {
        const int V = g ? V1 : V0;
        float4 v[4];
        int kr[4];
#pragma unroll
        for (int j = 0; j < 4; j++) {
            int cid = tid + 128 * j;
            int k = cid >> 4;
            kr[j] = k;
            int id = (k < V) ? s_idx[g][k] : 0;
            v[j] = *reinterpret_cast<const float4*>(featb + (size_t)id * CC + (cid & 15) * 4);
        }
#pragma unroll
        for (int j = 0; j < 4; j++) {
            int cid = tid + 128 * j;
            int k = kr[j], c16 = cid & 15;
            int kcol = (k & 3) + 4 * ((k >> 2) ^ (c16 & 7));  // S(row)=c16&7
            int r0 = 3 + 4 * c16;
            s_XT[g][r0 + 0][kcol] = v[j].x;
            s_XT[g][r0 + 1][kcol] = v[j].y;
            s_XT[g][r0 + 2][kcol] = v[j].z;
            s_XT[g][r0 + 3][kcol] = v[j].w;
        }
    }
    // rel-pos rows 0..2 (S=0 -> col=k): threads 0..63
    if (tid < G * KK) {
        int g = tid >> 5, k = tid & 31;
        int Vg = g ? V1 : V0;
        if (k < Vg) {
            const float* cp = centers   + ((size_t)b * MM + m0 + g) * 3;
            const float* pp = positions + ((size_t)b * NN + s_idx[g][k]) * 3;
            s_XT[g][0][k] = pp[0] - cp[0];
            s_XT[g][1][k] = pp[1] - cp[1];
            s_XT[g][2][k] = pp[2] - cp[2];
        }
    }
    __syncthreads();

    // ---- Phase B: k-packed register-tiled GEMM ----
    // acc[g][p][cc]: p=0 -> k-pair (4ktg,4ktg+1), p=1 -> (4ktg+2,4ktg+3)
    ull acc[G][2][4];
#pragma unroll
    for (int g = 0; g < G; g++)
#pragma unroll
        for (int p = 0; p < 2; p++)
#pragma unroll
            for (int cc = 0; cc < 4; cc++) acc[g][p][cc] = 0ull;

    // feature rows 3..66 in 16 blocks of 4; S = ib&7, xcol = 4*(ktg^S)
#pragma unroll 8
    for (int ib = 0; ib < 16; ib++) {
        const int xcol = 4 * (ktg ^ (ib & 7));
#pragma unroll
        for (int rr = 0; rr < 4; rr++) {
            const int row = 3 + 4 * ib + rr;
            ulonglong2 xu0 = *reinterpret_cast<const ulonglong2*>(&s_XT[0][row][xcol]);
            ulonglong2 xu1 = *reinterpret_cast<const ulonglong2*>(&s_XT[1][row][xcol]);
            float4 w4 = __ldg(reinterpret_cast<const float4*>(W_op + (size_t)row * COP + cb));
            ull w0 = dupf(w4.x), w1 = dupf(w4.y), w2 = dupf(w4.z), w3 = dupf(w4.w);
            ffma2p(acc[0][0][0], xu0.x, w0); ffma2p(acc[0][1][0], xu0.y, w0);
            ffma2p(acc[1][0][0], xu1.x, w0); ffma2p(acc[1][1][0], xu1.y, w0);
            ffma2p(acc[0][0][1], xu0.x, w1); ffma2p(acc[0][1][1], xu0.y, w1);
            ffma2p(acc[1][0][1], xu1.x, w1); ffma2p(acc[1][1][1], xu1.y, w1);
            ffma2p(acc[0][0][2], xu0.x, w2); ffma2p(acc[0][1][2], xu0.y, w2);
            ffma2p(acc[1][0][2], xu1.x, w2); ffma2p(acc[1][1][2], xu1.y, w2);
            ffma2p(acc[0][0][3], xu0.x, w3); ffma2p(acc[0][1][3], xu0.y, w3);
            ffma2p(acc[1][0][3], xu1.x, w3); ffma2p(acc[1][1][3], xu1.y, w3);
        }
    }
    // rel rows 0..2 (S=0 -> xcol = 4*ktg)
    {
        const int xcol = 4 * ktg;
#pragma unroll
        for (int row = 0; row < 3; row++) {
            ulonglong2 xu0 = *reinterpret_cast<const ulonglong2*>(&s_XT[0][row][xcol]);
            ulonglong2 xu1 = *reinterpret_cast<const ulonglong2*>(&s_XT[1][row][xcol]);
            float4 w4 = __ldg(reinterpret_cast<const float4*>(W_op + (size_t)row * COP + cb));
            ull w0 = dupf(w4.x), w1 = dupf(w4.y), w2 = dupf(w4.z), w3 = dupf(w4.w);
            ffma2p(acc[0][0][0], xu0.x, w0); ffma2p(acc[0][1][0], xu0.y, w0);
            ffma2p(acc[1][0][0], xu1.x, w0); ffma2p(acc[1][1][0], xu1.y, w0);
            ffma2p(acc[0][0][1], xu0.x, w1); ffma2p(acc[0][1][1], xu0.y, w1);
            ffma2p(acc[1][0][1], xu1.x, w1); ffma2p(acc[1][1][1], xu1.y, w1);
            ffma2p(acc[0][0][2], xu0.x, w2); ffma2p(acc[0][1][2], xu0.y, w2);
            ffma2p(acc[1][0][2], xu1.x, w2); ffma2p(acc[1][1][2], xu1.y, w2);
            ffma2p(acc[0][0][3], xu0.x, w3); ffma2p(acc[0][1][3], xu0.y, w3);
            ffma2p(acc[1][0][3], xu1.x, w3); ffma2p(acc[1][1][3], xu1.y, w3);
        }
    }

    // ---- bias + masked max over this thread's 4 k's, reduce over ktg lanes ----
    float4 bo = __ldg(reinterpret_cast<const float4*>(b_op + cb));
    const float bv[4] = { bo.x, bo.y, bo.z, bo.w };
    const int kb = 4 * ktg;
#pragma unroll
    for (int g = 0; g < G; g++) {
        const int V = g ? V1 : V0;
        bool v0 = kb < V, v1 = kb + 1 < V, v2 = kb + 2 < V, v3 = kb + 3 < V;
        float mx[4];
#pragma unroll
        for (int cc = 0; cc < 4; cc++) {
            float2 f01 = *reinterpret_cast<float2*>(&acc[g][0][cc]);
            float2 f23 = *reinterpret_cast<float2*>(&acc[g][1][cc]);
            float m = -FLT_MAX;
            if (v0) m = fmaxf(m, f01.x + bv[cc]);
            if (v1) m = fmaxf(m, f01.y + bv[cc]);
            if (v2) m = fmaxf(m, f23.x + bv[cc]);
            if (v3) m = fmaxf(m, f23.y + bv[cc]);
            mx[cc] = m;
        }
#pragma unroll
        for (int d = 1; d < 8; d <<= 1)
#pragma unroll
            for (int cc = 0; cc < 4; cc++)
                mx[cc] = fmaxf(mx[cc], __shfl_xor_sync(0xffffffffu, mx[cc], d));
        if (ktg == 0) {
            float z = (V < KK) ? 0.f : -FLT_MAX;
            *reinterpret_cast<float4*>(&s_pool[g][cb]) =
                make_float4(fmaxf(mx[0], z), fmaxf(mx[1], z),
                            fmaxf(mx[2], z), fmaxf(mx[3], z));
        }
    }
    __syncthreads();

    // ---- Phase C: aggregator (64 -> 128) + ReLU; W_agg shared by both centers ----
    float accA = b_agg[tid], accB = accA;
    const float4* p40 = reinterpret_cast<const float4*>(s_pool[0]);
    const float4* p41 = reinterpret_cast<const float4*>(s_pool[1]);
#pragma unroll
    for (int q = 0; q < 16; q++) {
        float4 pA = p40[q];
        float4 pB = p41[q];
        float w0 = __ldg(&W_agg[(4 * q + 0) * COUT + tid]);
        float w1 = __ldg(&W_agg[(4 * q + 1) * COUT + tid]);
        float w2 = __ldg(&W_agg[(4 * q + 2) * COUT + tid]);
        float w3 = __ldg(&W_agg[(4 * q + 3) * COUT + tid]);
        accA = fmaf(pA.x, w0, accA); accB = fmaf(pB.x, w0, accB);
        accA = fmaf(pA.y, w1, accA); accB = fmaf(pB.y, w1, accB);
        accA = fmaf(pA.z, w2, accA); accB = fmaf(pB.z, w2, accB);
        accA = fmaf(pA.w, w3, accA); accB = fmaf(pB.w, w3, accB);
    }
    size_t obase = ((size_t)b * MM + m0) * COUT + tid;
    out[obase]        = fmaxf(accA, 0.f);
    out[obase + COUT] = fmaxf(accB, 0.f);
}

extern "C" void kernel_launch(void* const* d_in, const int* in_sizes, int n_in,
                              void* d_out, int out_size)
{
    (void)in_sizes; (void)n_in; (void)out_size;
    pointnet_sampler_kernel<<<BB * MM / G, 128>>>(
        (const float*)d_in[0],  // positions
        (const float*)d_in[1],  // features
        (const float*)d_in[2],  // centers
        (const float*)d_in[3],  // distances
        (const float*)d_in[4],  // W_op
        (const float*)d_in[5],  // b_op
        (const float*)d_in[6],  // W_agg
        (const float*)d_in[7],  // b_agg
        (float*)d_out);
}

// round 8
// speedup vs baseline: 2.1378x; 1.0325x over previous
#include <cuda_runtime.h>
#include <cfloat>

#define BB    4
#define NN    16384
#define MM    1024
#define CC    64
#define COP   64
#define COUT  128
#define KK    32
#define R2    0.25f
#define XTS   36        // X^T row stride in floats (144B)
#define WPC   4         // warps (= centers) per CTA

typedef unsigned long long ull;

// In-place packed dual-FMA: d.{lo,hi} += x.{lo,hi} * w.{lo,hi}
__device__ __forceinline__ void ffma2p(ull& d, ull x, ull w) {
    asm("fma.rn.f32x2 %0, %1, %2, %0;" : "+l"(d) : "l"(x), "l"(w));
}
__device__ __forceinline__ ull dupf(float w) {
    ull r;
    asm("mov.b64 %0, {%1, %1};" : "=l"(r) : "f"(w));
    return r;
}

__global__ __launch_bounds__(128, 4)
void pointnet_sampler_kernel(
    const float* __restrict__ positions,   // (B, N, 3)
    const float* __restrict__ features,    // (B, N, 64)
    const float* __restrict__ centers,     // (B, M, 3)
    const float* __restrict__ distances,   // (B, M, N)
    const float* __restrict__ W_op,        // (67, 64): rows 0..2 rel, 3..66 feat
    const float* __restrict__ b_op,        // (64)
    const float* __restrict__ W_agg,       // (64, 128)
    const float* __restrict__ b_agg,       // (128)
    float* __restrict__ out)               // (B, M, 128)
{
    const int tid  = threadIdx.x;
    const int lane = tid & 31;
    const int wid  = tid >> 5;
    const int gw   = blockIdx.x * WPC + wid;   // global center index (0..4095)
    const int b    = gw >> 10;
    const int m    = gw & (MM - 1);
    const int ktg  = lane >> 3;                // k-tile: k in [8ktg, 8ktg+8)
    const int ct   = lane & 7;                 // c-tile: c in [8ct, 8ct+8)

    // X^T[i][col]: rows 0..2 = rel (col = k), rows 3+4*c16+rr = features,
    // feature col = (k&3) + 4*((k>>2) ^ (c16&6))  (even-XOR swizzle)
    __shared__ __align__(16) float s_XT[WPC][67][XTS];
    __shared__ int   s_idx[WPC][KK];
    __shared__ float s_pool[COP][6];   // [cc][g0 g1 g2 g3 pad pad]

    // ---- Phase A: ball query (warp-local) ----
    const float* drow = distances + ((size_t)b * MM + m) * NN;
    float dv[8];
#pragma unroll
    for (int j = 0; j < 8; j++) dv[j] = drow[j * 32 + lane];

    int count = 0;
#pragma unroll
    for (int j = 0; j < 8; j++) {
        if (count < KK) {                      // warp-uniform
            bool v = dv[j] < R2;
            unsigned msk = __ballot_sync(0xffffffffu, v);
            int pre = __popc(msk & ((1u << lane) - 1u));
            if (v && count + pre < KK) s_idx[wid][count + pre] = j * 32 + lane;
            count += __popc(msk);
        }
    }
    int base = 256;
    while (count < KK && base < NN) {          // rare fallback (~1% of rows)
        float d = drow[base + lane];
        bool v = d < R2;
        unsigned msk = __ballot_sync(0xffffffffu, v);
        int pre = __popc(msk & ((1u << lane) - 1u));
        if (v && count + pre < KK) s_idx[wid][count + pre] = base + lane;
        count += __popc(msk);
        base += 32;
    }
    const int V = min(count, KK);              // warp-uniform
    __syncwarp();

    // ---- rel-pos rows 0..2 (col = k, no swizzle) ----
    if (lane < V) {
        const float* cp = centers   + ((size_t)b * MM + m) * 3;
        const float* pp = positions + ((size_t)b * NN + s_idx[wid][lane]) * 3;
        s_XT[wid][0][lane] = pp[0] - cp[0];
        s_XT[wid][1][lane] = pp[1] - cp[1];
        s_XT[wid][2][lane] = pp[2] - cp[2];
    }

    // ---- feature gather: 32 rows x 16 chunks, 2 rows per inst, swizzled scatter ----
    {
        const float* featb = features + (size_t)b * NN * CC;
        const int c16 = lane & 15;
        const int khalf = lane >> 4;
#pragma unroll
        for (int jb = 0; jb < 4; jb++) {
            float4 v[4];
            int kk[4];
#pragma unroll
            for (int jj = 0; jj < 4; jj++) {
                int j = 4 * jb + jj;
                int k = 2 * j + khalf;
                kk[jj] = k;
                int id = (k < V) ? s_idx[wid][k] : 0;
                v[jj] = *reinterpret_cast<const float4*>(
                    featb + (size_t)id * CC + c16 * 4);
            }
#pragma unroll
            for (int jj = 0; jj < 4; jj++) {
                int k = kk[jj];
                int kcol = (k & 3) + 4 * ((k >> 2) ^ (c16 & 6));
                int r0 = 3 + 4 * c16;
                s_XT[wid][r0 + 0][kcol] = v[jj].x;
                s_XT[wid][r0 + 1][kcol] = v[jj].y;
                s_XT[wid][r0 + 2][kcol] = v[jj].z;
                s_XT[wid][r0 + 3][kcol] = v[jj].w;
            }
        }
    }
    __syncwarp();

    // ---- Phase B: 8k x 8c register-tiled GEMM (along-k f32x2 pairs) ----
    // acc[p][c]: k-pair (8ktg+2p, 8ktg+2p+1), channel 8ct+c
    ull acc[4][8];
#pragma unroll
    for (int p = 0; p < 4; p++)
#pragma unroll
        for (int c = 0; c < 8; c++) acc[p][c] = 0ull;

    const float* xtw = &s_XT[wid][0][0];
    const float* wop = W_op + 8 * ct;

#pragma unroll 2
    for (int ib = 0; ib < 16; ib++) {
        const int colf = 4 * ((2 * ktg) ^ (ib & 6));   // physical col of this thread's 8 k's
#pragma unroll
        for (int rr = 0; rr < 4; rr++) {
            const int row = 3 + 4 * ib + rr;
            const float* xr = xtw + row * XTS + colf;
            ulonglong2 xA = *reinterpret_cast<const ulonglong2*>(xr);      // pairs p0,p1
            ulonglong2 xB = *reinterpret_cast<const ulonglong2*>(xr + 4);  // pairs p2,p3
            float4 wA = __ldg(reinterpret_cast<const float4*>(wop + (size_t)row * COP));
            float4 wB = __ldg(reinterpret_cast<const float4*>(wop + (size_t)row * COP + 4));
            ull w0 = dupf(wA.x), w1 = dupf(wA.y), w2 = dupf(wA.z), w3 = dupf(wA.w);
            ull w4 = dupf(wB.x), w5 = dupf(wB.y), w6 = dupf(wB.z), w7 = dupf(wB.w);
            ffma2p(acc[0][0], xA.x, w0); ffma2p(acc[1][0], xA.y, w0);
            ffma2p(acc[2][0], xB.x, w0); ffma2p(acc[3][0], xB.y, w0);
            ffma2p(acc[0][1], xA.x, w1); ffma2p(acc[1][1], xA.y, w1);
            ffma2p(acc[2][1], xB.x, w1); ffma2p(acc[3][1], xB.y, w1);
            ffma2p(acc[0][2], xA.x, w2); ffma2p(acc[1][2], xA.y, w2);
            ffma2p(acc[2][2], xB.x, w2); ffma2p(acc[3][2], xB.y, w2);
            ffma2p(acc[0][3], xA.x, w3); ffma2p(acc[1][3], xA.y, w3);
            ffma2p(acc[2][3], xB.x, w3); ffma2p(acc[3][3], xB.y, w3);
            ffma2p(acc[0][4], xA.x, w4); ffma2p(acc[1][4], xA.y, w4);
            ffma2p(acc[2][4], xB.x, w4); ffma2p(acc[3][4], xB.y, w4);
            ffma2p(acc[0][5], xA.x, w5); ffma2p(acc[1][5], xA.y, w5);
            ffma2p(acc[2][5], xB.x, w5); ffma2p(acc[3][5], xB.y, w5);
            ffma2p(acc[0][6], xA.x, w6); ffma2p(acc[1][6], xA.y, w6);
            ffma2p(acc[2][6], xB.x, w6); ffma2p(acc[3][6], xB.y, w6);
            ffma2p(acc[0][7], xA.x, w7); ffma2p(acc[1][7], xA.y, w7);
            ffma2p(acc[2][7], xB.x, w7); ffma2p(acc[3][7], xB.y, w7);
        }
    }
    // rel tail: X^T rows 0..2 (cols natural), W rows 0..2
#pragma unroll
    for (int row = 0; row < 3; row++) {
        const float* xr = xtw + row * XTS + 8 * ktg;
        ulonglong2 xA = *reinterpret_cast<const ulonglong2*>(xr);
        ulonglong2 xB = *reinterpret_cast<const ulonglong2*>(xr + 4);
        float4 wA = __ldg(reinterpret_cast<const float4*>(wop + (size_t)row * COP));
        float4 wB = __ldg(reinterpret_cast<const float4*>(wop + (size_t)row * COP + 4));
        ull wv[8] = { dupf(wA.x), dupf(wA.y), dupf(wA.z), dupf(wA.w),
                      dupf(wB.x), dupf(wB.y), dupf(wB.z), dupf(wB.w) };
#pragma unroll
        for (int c = 0; c < 8; c++) {
            ffma2p(acc[0][c], xA.x, wv[c]); ffma2p(acc[1][c], xA.y, wv[c]);
            ffma2p(acc[2][c], xB.x, wv[c]); ffma2p(acc[3][c], xB.y, wv[c]);
        }
    }

    // ---- bias + masked max over this thread's 8 k's, reduce over ktg lanes ----
    {
        float4 bA = __ldg(reinterpret_cast<const float4*>(b_op + 8 * ct));
        float4 bB = __ldg(reinterpret_cast<const float4*>(b_op + 8 * ct + 4));
        const float bv[8] = { bA.x, bA.y, bA.z, bA.w, bB.x, bB.y, bB.z, bB.w };
        float mx[8];
#pragma unroll
        for (int c = 0; c < 8; c++) mx[c] = -FLT_MAX;
#pragma unroll
        for (int p = 0; p < 4; p++) {
            bool vlo = (8 * ktg + 2 * p)     < V;
            bool vhi = (8 * ktg + 2 * p + 1) < V;
#pragma unroll
            for (int c = 0; c < 8; c++) {
                float2 f = *reinterpret_cast<float2*>(&acc[p][c]);
                if (vlo) mx[c] = fmaxf(mx[c], f.x + bv[c]);
                if (vhi) mx[c] = fmaxf(mx[c], f.y + bv[c]);
            }
        }
#pragma unroll
        for (int d = 8; d < 32; d <<= 1)
#pragma unroll
            for (int c = 0; c < 8; c++)
                mx[c] = fmaxf(mx[c], __shfl_xor_sync(0xffffffffu, mx[c], d));
        // zero row participates iff some slot invalid
        float z = (V < KK) ? 0.f : -FLT_MAX;
        if (ktg == 0) {
#pragma unroll
            for (int c = 0; c < 8; c++)
                s_pool[8 * ct + c][wid] = fmaxf(mx[c], z);
        }
    }
    __syncthreads();

    // ---- Phase C: cooperative aggregator, 4 centers share each W_agg read ----
    {
        ull acc01 = dupf(b_agg[tid]);
        ull acc23 = acc01;
#pragma unroll 8
        for (int cc = 0; cc < COP; cc++) {
            ull wd  = dupf(__ldg(&W_agg[(size_t)cc * COUT + tid]));
            ull p01 = *reinterpret_cast<const ull*>(&s_pool[cc][0]);
            ull p23 = *reinterpret_cast<const ull*>(&s_pool[cc][2]);
            ffma2p(acc01, p01, wd);
            ffma2p(acc23, p23, wd);
        }
        float2 r01 = *reinterpret_cast<float2*>(&acc01);
        float2 r23 = *reinterpret_cast<float2*>(&acc23);
        const int mbase = (blockIdx.x * WPC) & (MM - 1);
        size_t obase = ((size_t)b * MM + mbase) * COUT + tid;
        out[obase + 0 * COUT] = fmaxf(r01.x, 0.f);
        out[obase + 1 * COUT] = fmaxf(r01.y, 0.f);
        out[obase + 2 * COUT] = fmaxf(r23.x, 0.f);
        out[obase + 3 * COUT] = fmaxf(r23.y, 0.f);
    }
}

extern "C" void kernel_launch(void* const* d_in, const int* in_sizes, int n_in,
                              void* d_out, int out_size)
{
    (void)in_sizes; (void)n_in; (void)out_size;
    pointnet_sampler_kernel<<<BB * MM / WPC, 128>>>(
        (const float*)d_in[0],  // positions
        (const float*)d_in[1],  // features
        (const float*)d_in[2],  // centers
        (const float*)d_in[3],  // distances
        (const float*)d_in[4],  // W_op
        (const float*)d_in[5],  // b_op
        (const float*)d_in[6],  // W_agg
        (const float*)d_in[7],  // b_agg
        (float*)d_out);
}